// round 3
// baseline (speedup 1.0000x reference)
#include <cuda_runtime.h>

// EfConv: out[n, k*64+o] = sum_{e: dst_e=n} ef[e,k] * (node_feat[src_e] . W[o]) + b[o]
// y = X @ W^T first (8x smaller GEMM). CSR-by-dst with 8-aligned segments
// (zero-padded), permuted src + ef payload so the main pass streams ef and
// batches 8 independent y-gathers per iteration (no tail, no atomics).

#define MAXN 50000
#define MAXE 800000
#define NF 64
#define ED 8
#define MAXP (MAXE + 8 * MAXN)   // padded edge capacity

// Scratch (static __device__ arrays; no allocation anywhere)
__device__ int   g_deg[MAXN];
__device__ int   g_off[MAXN + 1];
__device__ int   g_cur[MAXN];
__device__ int   g_srcP[MAXP];                 // permuted src, 8-aligned segments
__device__ float g_efP[(size_t)MAXP * ED];     // permuted ef rows (38 MB)
__device__ float g_y[(size_t)MAXN * NF];       // 12.8 MB, L2-resident

// ---------------- CSR build ----------------

__global__ void k_zero_deg(int N) {
    int i = blockIdx.x * blockDim.x + threadIdx.x;
    if (i < N) g_deg[i] = 0;
}

__global__ void k_hist(const int* __restrict__ dst, int E) {
    int t = blockIdx.x * blockDim.x + threadIdx.x;
    int e = t * 4;
    if (e + 4 <= E) {
        int4 d = *(const int4*)(dst + e);
        atomicAdd(&g_deg[d.x], 1);
        atomicAdd(&g_deg[d.y], 1);
        atomicAdd(&g_deg[d.z], 1);
        atomicAdd(&g_deg[d.w], 1);
    } else {
        for (; e < E; e++) atomicAdd(&g_deg[dst[e]], 1);
    }
}

// Single-block scan; segment sizes rounded up to multiples of 8.
__global__ void k_scan(int N) {
    __shared__ int sh[1024];
    int t = threadIdx.x;
    int chunk = (N + 1023) / 1024;
    int beg = t * chunk;
    int end = min(beg + chunk, N);
    int s = 0;
    for (int i = beg; i < end; i++) s += (g_deg[i] + 7) & ~7;
    sh[t] = s;
    __syncthreads();
    for (int d = 1; d < 1024; d <<= 1) {
        int v = (t >= d) ? sh[t - d] : 0;
        __syncthreads();
        sh[t] += v;
        __syncthreads();
    }
    int run = (t == 0) ? 0 : sh[t - 1];
    for (int i = beg; i < end; i++) {
        g_off[i] = run;
        g_cur[i] = run;
        run += (g_deg[i] + 7) & ~7;
    }
    if (t == 1023) g_off[N] = run;
}

// Zero the pad slots (<=7 per node) so padded edges contribute exactly 0.
__global__ void k_pad(int N) {
    int idx = blockIdx.x * blockDim.x + threadIdx.x;
    int i = idx >> 3, s = idx & 7;
    if (i >= N) return;
    int p = g_off[i] + g_deg[i] + s;
    if (p < g_off[i + 1]) {
        g_srcP[p] = 0;
        float4 z = make_float4(0.f, 0.f, 0.f, 0.f);
        float4* o4 = (float4*)(g_efP + (size_t)p * ED);
        o4[0] = z;
        o4[1] = z;
    }
}

// Scatter src + ef row into dst-grouped (8-aligned) order.
__global__ void k_scatter(const int* __restrict__ src, const int* __restrict__ dst,
                          const float* __restrict__ ef, int E) {
    int e = blockIdx.x * blockDim.x + threadIdx.x;
    if (e >= E) return;
    int pos = atomicAdd(&g_cur[dst[e]], 1);
    g_srcP[pos] = src[e];
    const float4* s4 = (const float4*)(ef + (size_t)e * ED);
    float4 a = s4[0], c = s4[1];
    float4* o4 = (float4*)(g_efP + (size_t)pos * ED);
    o4[0] = a;
    o4[1] = c;
}

// ---------------- y = X @ W^T ----------------
__global__ void k_ygemm(const float* __restrict__ X, const float* __restrict__ W, int N) {
    __shared__ float Ws[64][68];
    __shared__ float xs[16][64];
    int t = threadIdx.x;
    int base = blockIdx.x * 16;

    for (int idx = t; idx < 64 * 64; idx += 256)
        Ws[idx >> 6][idx & 63] = W[idx];
    for (int idx = t; idx < 16 * 64; idx += 256) {
        int ln = idx >> 6, i = idx & 63;
        int n = base + ln;
        xs[ln][i] = (n < N) ? X[(size_t)n * NF + i] : 0.f;
    }
    __syncthreads();

    int o = t & 63;
    int g = t >> 6;
    float acc[4] = {0.f, 0.f, 0.f, 0.f};
    #pragma unroll
    for (int i = 0; i < 64; i += 4) {
        float4 wv = *(const float4*)&Ws[o][i];
        #pragma unroll
        for (int r = 0; r < 4; r++) {
            float4 xv = *(const float4*)&xs[g * 4 + r][i];
            acc[r] += wv.x * xv.x + wv.y * xv.y + wv.z * xv.z + wv.w * xv.w;
        }
    }
    #pragma unroll
    for (int r = 0; r < 4; r++) {
        int n = base + g * 4 + r;
        if (n < N) g_y[(size_t)n * NF + o] = acc[r];
    }
}

// ---------------- main: warp-per-node, 8-edge batches ----------------
__device__ __forceinline__ void fma_edge(float (&acc)[16], float4 ea, float4 eb, float2 yv) {
    acc[0]  += ea.x * yv.x;  acc[1]  += ea.x * yv.y;
    acc[2]  += ea.y * yv.x;  acc[3]  += ea.y * yv.y;
    acc[4]  += ea.z * yv.x;  acc[5]  += ea.z * yv.y;
    acc[6]  += ea.w * yv.x;  acc[7]  += ea.w * yv.y;
    acc[8]  += eb.x * yv.x;  acc[9]  += eb.x * yv.y;
    acc[10] += eb.y * yv.x;  acc[11] += eb.y * yv.y;
    acc[12] += eb.z * yv.x;  acc[13] += eb.z * yv.y;
    acc[14] += eb.w * yv.x;  acc[15] += eb.w * yv.y;
}

__global__ void __launch_bounds__(256, 4) k_main(const float* __restrict__ bvec,
                                                 float* __restrict__ out, int N) {
    int w = (blockIdx.x * blockDim.x + threadIdx.x) >> 5;
    if (w >= N) return;
    int lane = threadIdx.x & 31;
    int beg = g_off[w], end = g_off[w + 1];   // both multiples of 8

    float acc[16];
    #pragma unroll
    for (int a = 0; a < 16; a++) acc[a] = 0.f;

    const float* yb = g_y + lane * 2;

    for (int j = beg; j < end; j += 8) {
        int4 s0 = *(const int4*)(g_srcP + j);       // aligned: j % 8 == 0
        int4 s1 = *(const int4*)(g_srcP + j + 4);
        // 8 independent y gathers (coalesced 256B each, L2-resident)
        float2 y0 = *(const float2*)(yb + (size_t)s0.x * NF);
        float2 y1 = *(const float2*)(yb + (size_t)s0.y * NF);
        float2 y2 = *(const float2*)(yb + (size_t)s0.z * NF);
        float2 y3 = *(const float2*)(yb + (size_t)s0.w * NF);
        float2 y4 = *(const float2*)(yb + (size_t)s1.x * NF);
        float2 y5 = *(const float2*)(yb + (size_t)s1.y * NF);
        float2 y6 = *(const float2*)(yb + (size_t)s1.z * NF);
        float2 y7 = *(const float2*)(yb + (size_t)s1.w * NF);
        // ef: 256B contiguous stream, consumed transiently
        const float4* ep = (const float4*)(g_efP + (size_t)j * ED);
        fma_edge(acc, ep[0],  ep[1],  y0);
        fma_edge(acc, ep[2],  ep[3],  y1);
        fma_edge(acc, ep[4],  ep[5],  y2);
        fma_edge(acc, ep[6],  ep[7],  y3);
        fma_edge(acc, ep[8],  ep[9],  y4);
        fma_edge(acc, ep[10], ep[11], y5);
        fma_edge(acc, ep[12], ep[13], y6);
        fma_edge(acc, ep[14], ep[15], y7);
    }

    float2 bb = *(const float2*)(bvec + lane * 2);
    float* op = out + (size_t)w * (ED * NF);
    #pragma unroll
    for (int k = 0; k < ED; k++) {
        float2 v;
        v.x = acc[2 * k]     + bb.x;
        v.y = acc[2 * k + 1] + bb.y;
        *(float2*)(op + k * NF + lane * 2) = v;
    }
}

// ---------------- launch ----------------

extern "C" void kernel_launch(void* const* d_in, const int* in_sizes, int n_in,
                              void* d_out, int out_size) {
    const float* node_feat = (const float*)d_in[0];
    const float* edge_feat = (const float*)d_in[1];
    const float* W         = (const float*)d_in[2];
    const float* b         = (const float*)d_in[3];
    const int*   src       = (const int*)d_in[4];
    const int*   dst       = (const int*)d_in[5];

    int N = in_sizes[0] / NF;     // 50000
    int E = in_sizes[4];          // 800000

    k_zero_deg<<<(N + 255) / 256, 256>>>(N);
    k_hist   <<<(E / 4 + 255) / 256, 256>>>(dst, E);
    k_scan   <<<1, 1024>>>(N);
    k_pad    <<<(N * 8 + 255) / 256, 256>>>(N);
    k_scatter<<<(E + 255) / 256, 256>>>(src, dst, edge_feat, E);
    k_ygemm  <<<(N + 15) / 16, 256>>>(node_feat, W, N);
    k_main   <<<(N * 32 + 255) / 256, 256>>>(b, (float*)d_out, N);
}

// round 4
// speedup vs baseline: 1.1067x; 1.1067x over previous
#include <cuda_runtime.h>

// EfConv: out[n, k*64+o] = sum_{e: dst_e=n} ef[e,k] * (node_feat[src_e] . W[o]) + b[o]
// y = X @ W^T first (8x smaller GEMM). CSR-by-dst with 8-aligned zero-padded
// segments; permuted src + ef payload; warp-per-node main pass with 8-edge
// batches. Scan is a coalesced 3-pass block scan (the old single-block strided
// scan was a ~100us serial bottleneck).

#define MAXN 50000
#define MAXE 800000
#define NF 64
#define ED 8
#define MAXP (MAXE + 8 * MAXN)   // padded edge capacity
#define SCAN_B 1024
#define MAX_BLKS 64              // ceil(50000/1024) = 49

// Scratch (static __device__ arrays; no allocation anywhere)
__device__ int   g_deg[MAXN];
__device__ int   g_off[MAXN + 1];
__device__ int   g_cur[MAXN];
__device__ int   g_bsum[MAX_BLKS];
__device__ int   g_boff[MAX_BLKS];
__device__ int   g_srcP[MAXP];                 // permuted src, 8-aligned segments
__device__ float g_efP[(size_t)MAXP * ED];     // permuted ef rows (~38 MB)
__device__ float g_y[(size_t)MAXN * NF];       // 12.8 MB, L2-resident

// ---------------- CSR build ----------------

__global__ void k_zero_deg(int N) {
    int i = blockIdx.x * blockDim.x + threadIdx.x;
    if (i < N) g_deg[i] = 0;
}

__global__ void k_hist(const int* __restrict__ dst, int E) {
    int t = blockIdx.x * blockDim.x + threadIdx.x;
    int e = t * 4;
    if (e + 4 <= E) {
        int4 d = *(const int4*)(dst + e);
        atomicAdd(&g_deg[d.x], 1);
        atomicAdd(&g_deg[d.y], 1);
        atomicAdd(&g_deg[d.z], 1);
        atomicAdd(&g_deg[d.w], 1);
    } else {
        for (; e < E; e++) atomicAdd(&g_deg[dst[e]], 1);
    }
}

// Pass A: per-block inclusive scan of padded degrees (coalesced).
__global__ void k_scanA(int N) {
    __shared__ int sh[SCAN_B];
    int t = threadIdx.x;
    int i = blockIdx.x * SCAN_B + t;
    int v = (i < N) ? ((g_deg[i] + 7) & ~7) : 0;
    sh[t] = v;
    __syncthreads();
    for (int d = 1; d < SCAN_B; d <<= 1) {
        int u = (t >= d) ? sh[t - d] : 0;
        __syncthreads();
        sh[t] += u;
        __syncthreads();
    }
    if (i < N) g_off[i] = sh[t] - v;             // exclusive local prefix
    if (t == SCAN_B - 1) g_bsum[blockIdx.x] = sh[SCAN_B - 1];
}

// Pass B: scan the (<=64) block sums; also writes total to g_off[N].
__global__ void k_scanB(int NB, int N) {
    __shared__ int sh[MAX_BLKS];
    int t = threadIdx.x;
    int v = (t < NB) ? g_bsum[t] : 0;
    sh[t] = v;
    __syncthreads();
    for (int d = 1; d < MAX_BLKS; d <<= 1) {
        int u = (t >= d) ? sh[t - d] : 0;
        __syncthreads();
        sh[t] += u;
        __syncthreads();
    }
    if (t < NB) g_boff[t] = sh[t] - v;
    if (t == MAX_BLKS - 1) g_off[N] = sh[MAX_BLKS - 1];
}

// Pass C: add block offsets back; copy to cursor (coalesced).
__global__ void k_scanC(int N) {
    int i = blockIdx.x * blockDim.x + threadIdx.x;
    if (i < N) {
        int o = g_off[i] + g_boff[i >> 10];
        g_off[i] = o;
        g_cur[i] = o;
    }
}

// Zero the pad slots (<=7 per node) so padded edges contribute exactly 0.
__global__ void k_pad(int N) {
    int idx = blockIdx.x * blockDim.x + threadIdx.x;
    int i = idx >> 3, s = idx & 7;
    if (i >= N) return;
    int p = g_off[i] + g_deg[i] + s;
    if (p < g_off[i + 1]) {
        g_srcP[p] = 0;
        float4 z = make_float4(0.f, 0.f, 0.f, 0.f);
        float4* o4 = (float4*)(g_efP + (size_t)p * ED);
        o4[0] = z;
        o4[1] = z;
    }
}

// Scatter src + ef row into dst-grouped (8-aligned) order.
__global__ void k_scatter(const int* __restrict__ src, const int* __restrict__ dst,
                          const float* __restrict__ ef, int E) {
    int e = blockIdx.x * blockDim.x + threadIdx.x;
    if (e >= E) return;
    int pos = atomicAdd(&g_cur[dst[e]], 1);
    g_srcP[pos] = src[e];
    const float4* s4 = (const float4*)(ef + (size_t)e * ED);
    float4 a = s4[0], c = s4[1];
    float4* o4 = (float4*)(g_efP + (size_t)pos * ED);
    o4[0] = a;
    o4[1] = c;
}

// ---------------- y = X @ W^T ----------------
__global__ void k_ygemm(const float* __restrict__ X, const float* __restrict__ W, int N) {
    __shared__ float Ws[64][68];
    __shared__ float xs[16][64];
    int t = threadIdx.x;
    int base = blockIdx.x * 16;

    for (int idx = t; idx < 64 * 64; idx += 256)
        Ws[idx >> 6][idx & 63] = W[idx];
    for (int idx = t; idx < 16 * 64; idx += 256) {
        int ln = idx >> 6, i = idx & 63;
        int n = base + ln;
        xs[ln][i] = (n < N) ? X[(size_t)n * NF + i] : 0.f;
    }
    __syncthreads();

    int o = t & 63;
    int g = t >> 6;
    float acc[4] = {0.f, 0.f, 0.f, 0.f};
    #pragma unroll
    for (int i = 0; i < 64; i += 4) {
        float4 wv = *(const float4*)&Ws[o][i];
        #pragma unroll
        for (int r = 0; r < 4; r++) {
            float4 xv = *(const float4*)&xs[g * 4 + r][i];
            acc[r] += wv.x * xv.x + wv.y * xv.y + wv.z * xv.z + wv.w * xv.w;
        }
    }
    #pragma unroll
    for (int r = 0; r < 4; r++) {
        int n = base + g * 4 + r;
        if (n < N) g_y[(size_t)n * NF + o] = acc[r];
    }
}

// ---------------- main: warp-per-node, 8-edge batches ----------------
__device__ __forceinline__ void fma_edge(float (&acc)[16], float4 ea, float4 eb, float2 yv) {
    acc[0]  += ea.x * yv.x;  acc[1]  += ea.x * yv.y;
    acc[2]  += ea.y * yv.x;  acc[3]  += ea.y * yv.y;
    acc[4]  += ea.z * yv.x;  acc[5]  += ea.z * yv.y;
    acc[6]  += ea.w * yv.x;  acc[7]  += ea.w * yv.y;
    acc[8]  += eb.x * yv.x;  acc[9]  += eb.x * yv.y;
    acc[10] += eb.y * yv.x;  acc[11] += eb.y * yv.y;
    acc[12] += eb.z * yv.x;  acc[13] += eb.z * yv.y;
    acc[14] += eb.w * yv.x;  acc[15] += eb.w * yv.y;
}

__global__ void __launch_bounds__(256, 4) k_main(const float* __restrict__ bvec,
                                                 float* __restrict__ out, int N) {
    int w = (blockIdx.x * blockDim.x + threadIdx.x) >> 5;
    if (w >= N) return;
    int lane = threadIdx.x & 31;
    int beg = g_off[w], end = g_off[w + 1];   // both multiples of 8

    float acc[16];
    #pragma unroll
    for (int a = 0; a < 16; a++) acc[a] = 0.f;

    const float* yb = g_y + lane * 2;

    for (int j = beg; j < end; j += 8) {
        int4 s0 = *(const int4*)(g_srcP + j);
        int4 s1 = *(const int4*)(g_srcP + j + 4);
        float2 y0 = *(const float2*)(yb + (size_t)s0.x * NF);
        float2 y1 = *(const float2*)(yb + (size_t)s0.y * NF);
        float2 y2 = *(const float2*)(yb + (size_t)s0.z * NF);
        float2 y3 = *(const float2*)(yb + (size_t)s0.w * NF);
        float2 y4 = *(const float2*)(yb + (size_t)s1.x * NF);
        float2 y5 = *(const float2*)(yb + (size_t)s1.y * NF);
        float2 y6 = *(const float2*)(yb + (size_t)s1.z * NF);
        float2 y7 = *(const float2*)(yb + (size_t)s1.w * NF);
        const float4* ep = (const float4*)(g_efP + (size_t)j * ED);
        fma_edge(acc, ep[0],  ep[1],  y0);
        fma_edge(acc, ep[2],  ep[3],  y1);
        fma_edge(acc, ep[4],  ep[5],  y2);
        fma_edge(acc, ep[6],  ep[7],  y3);
        fma_edge(acc, ep[8],  ep[9],  y4);
        fma_edge(acc, ep[10], ep[11], y5);
        fma_edge(acc, ep[12], ep[13], y6);
        fma_edge(acc, ep[14], ep[15], y7);
    }

    float2 bb = *(const float2*)(bvec + lane * 2);
    float* op = out + (size_t)w * (ED * NF);
    #pragma unroll
    for (int k = 0; k < ED; k++) {
        float2 v;
        v.x = acc[2 * k]     + bb.x;
        v.y = acc[2 * k + 1] + bb.y;
        *(float2*)(op + k * NF + lane * 2) = v;
    }
}

// ---------------- launch ----------------

extern "C" void kernel_launch(void* const* d_in, const int* in_sizes, int n_in,
                              void* d_out, int out_size) {
    const float* node_feat = (const float*)d_in[0];
    const float* edge_feat = (const float*)d_in[1];
    const float* W         = (const float*)d_in[2];
    const float* b         = (const float*)d_in[3];
    const int*   src       = (const int*)d_in[4];
    const int*   dst       = (const int*)d_in[5];

    int N = in_sizes[0] / NF;     // 50000
    int E = in_sizes[4];          // 800000
    int NB = (N + SCAN_B - 1) / SCAN_B;

    k_zero_deg<<<(N + 255) / 256, 256>>>(N);
    k_hist   <<<(E / 4 + 255) / 256, 256>>>(dst, E);
    k_scanA  <<<NB, SCAN_B>>>(N);
    k_scanB  <<<1, MAX_BLKS>>>(NB, N);
    k_scanC  <<<(N + 255) / 256, 256>>>(N);
    k_pad    <<<(N * 8 + 255) / 256, 256>>>(N);
    k_scatter<<<(E + 255) / 256, 256>>>(src, dst, edge_feat, E);
    k_ygemm  <<<(N + 15) / 16, 256>>>(node_feat, W, N);
    k_main   <<<(N * 32 + 255) / 256, 256>>>(b, (float*)d_out, N);
}

// round 5
// speedup vs baseline: 1.6394x; 1.4813x over previous
#include <cuda_runtime.h>

// EfConv: out[n, k*64+o] = sum_{e: dst_e=n} ef[e,k] * (node_feat[src_e] . W[o]) + b[o]
// y = X @ W^T first. CSR-by-dst with 8-aligned zero-padded segments; permuted
// src + ef payload; warp-per-node main pass (8-edge batches).
// R5: conflict-free ygemm (transposed W, float4 smem reads), pad fused into
// scatter, ygemm placed at ncu capture slot (launch index 3).

#define MAXN 50000
#define MAXE 800000
#define NF 64
#define ED 8
#define MAXP (MAXE + 8 * MAXN)
#define SCAN_B 1024
#define MAX_BLKS 64

__device__ int   g_deg[MAXN];
__device__ int   g_off[MAXN + 1];
__device__ int   g_cur[MAXN];
__device__ int   g_bsum[MAX_BLKS];
__device__ int   g_boff[MAX_BLKS];
__device__ int   g_srcP[MAXP];
__device__ float g_efP[(size_t)MAXP * ED];
__device__ float g_y[(size_t)MAXN * NF];
__device__ float g_WT[NF * NF];              // W transposed: g_WT[i*64+o] = W[o*64+i]

// ---------------- W transpose (tiny) ----------------
__global__ void k_wt(const float* __restrict__ W) {
    int idx = blockIdx.x * blockDim.x + threadIdx.x;
    if (idx < NF * NF)
        g_WT[(idx & 63) * NF + (idx >> 6)] = W[idx];
}

__global__ void k_zero_deg(int N) {
    int i = blockIdx.x * blockDim.x + threadIdx.x;
    if (i < N) g_deg[i] = 0;
}

__global__ void k_hist(const int* __restrict__ dst, int E) {
    int t = blockIdx.x * blockDim.x + threadIdx.x;
    int e = t * 4;
    if (e + 4 <= E) {
        int4 d = *(const int4*)(dst + e);
        atomicAdd(&g_deg[d.x], 1);
        atomicAdd(&g_deg[d.y], 1);
        atomicAdd(&g_deg[d.z], 1);
        atomicAdd(&g_deg[d.w], 1);
    } else {
        for (; e < E; e++) atomicAdd(&g_deg[dst[e]], 1);
    }
}

// ---------------- y = X @ W^T : 32 nodes/block, conflict-free ----------------
__global__ void __launch_bounds__(256) k_ygemm(const float* __restrict__ X, int N) {
    __shared__ float WsT[NF * NF];    // 16 KB, [i*64+o]
    __shared__ float xs[32][NF];      // 8 KB
    int t = threadIdx.x;
    int base = blockIdx.x * 32;

    #pragma unroll
    for (int k = 0; k < 4; k++)
        ((float4*)WsT)[t + k * 256] = ((const float4*)g_WT)[t + k * 256];
    #pragma unroll
    for (int k = 0; k < 2; k++) {
        int idx = t + k * 256;                 // float4 index into xs (512 total)
        int ln = idx >> 4, q = idx & 15;       // node-local, quad
        int n = base + ln;
        float4 v = (n < N) ? ((const float4*)(X + (size_t)n * NF))[q]
                           : make_float4(0.f, 0.f, 0.f, 0.f);
        ((float4*)&xs[ln][0])[q] = v;
    }
    __syncthreads();

    int o4 = (t & 15) * 4;
    int slot = t >> 4;                         // 0..15
    float4 a0 = make_float4(0.f, 0.f, 0.f, 0.f);
    float4 a1 = make_float4(0.f, 0.f, 0.f, 0.f);
    #pragma unroll 8
    for (int i = 0; i < NF; i++) {
        float4 w = *(const float4*)&WsT[i * NF + o4];   // 256B contiguous per half-warp
        float x0 = xs[slot][i];                          // broadcast
        float x1 = xs[slot + 16][i];                     // broadcast
        a0.x += w.x * x0; a0.y += w.y * x0; a0.z += w.z * x0; a0.w += w.w * x0;
        a1.x += w.x * x1; a1.y += w.y * x1; a1.z += w.z * x1; a1.w += w.w * x1;
    }
    int n0 = base + slot, n1 = base + slot + 16;
    if (n0 < N) *(float4*)(g_y + (size_t)n0 * NF + o4) = a0;
    if (n1 < N) *(float4*)(g_y + (size_t)n1 * NF + o4) = a1;
}

// ---------------- scan (3-pass, coalesced) ----------------
__global__ void k_scanA(int N) {
    __shared__ int sh[SCAN_B];
    int t = threadIdx.x;
    int i = blockIdx.x * SCAN_B + t;
    int v = (i < N) ? ((g_deg[i] + 7) & ~7) : 0;
    sh[t] = v;
    __syncthreads();
    for (int d = 1; d < SCAN_B; d <<= 1) {
        int u = (t >= d) ? sh[t - d] : 0;
        __syncthreads();
        sh[t] += u;
        __syncthreads();
    }
    if (i < N) g_off[i] = sh[t] - v;
    if (t == SCAN_B - 1) g_bsum[blockIdx.x] = sh[SCAN_B - 1];
}

__global__ void k_scanB(int NB, int N) {
    __shared__ int sh[MAX_BLKS];
    int t = threadIdx.x;
    int v = (t < NB) ? g_bsum[t] : 0;
    sh[t] = v;
    __syncthreads();
    for (int d = 1; d < MAX_BLKS; d <<= 1) {
        int u = (t >= d) ? sh[t - d] : 0;
        __syncthreads();
        sh[t] += u;
        __syncthreads();
    }
    if (t < NB) g_boff[t] = sh[t] - v;
    if (t == MAX_BLKS - 1) g_off[N] = sh[MAX_BLKS - 1];
}

__global__ void k_scanC(int N) {
    int i = blockIdx.x * blockDim.x + threadIdx.x;
    if (i < N) {
        int o = g_off[i] + g_boff[i >> 10];
        g_off[i] = o;
        g_cur[i] = o;
    }
}

// ---------------- scatter + pad (fused) ----------------
__global__ void k_scatterpad(const int* __restrict__ src, const int* __restrict__ dst,
                             const float* __restrict__ ef, int E, int N) {
    int t = blockIdx.x * blockDim.x + threadIdx.x;
    if (t < E) {
        int pos = atomicAdd(&g_cur[dst[t]], 1);
        g_srcP[pos] = src[t];
        const float4* s4 = (const float4*)(ef + (size_t)t * ED);
        float4 a = s4[0], c = s4[1];
        float4* o4 = (float4*)(g_efP + (size_t)pos * ED);
        o4[0] = a;
        o4[1] = c;
    } else {
        int idx = t - E;
        int i = idx >> 3, s = idx & 7;
        if (i < N) {
            int p = g_off[i] + g_deg[i] + s;
            if (p < g_off[i + 1]) {
                g_srcP[p] = 0;
                float4 z = make_float4(0.f, 0.f, 0.f, 0.f);
                float4* o4 = (float4*)(g_efP + (size_t)p * ED);
                o4[0] = z;
                o4[1] = z;
            }
        }
    }
}

// ---------------- main: warp-per-node, 8-edge batches ----------------
__device__ __forceinline__ void fma_edge(float (&acc)[16], float4 ea, float4 eb, float2 yv) {
    acc[0]  += ea.x * yv.x;  acc[1]  += ea.x * yv.y;
    acc[2]  += ea.y * yv.x;  acc[3]  += ea.y * yv.y;
    acc[4]  += ea.z * yv.x;  acc[5]  += ea.z * yv.y;
    acc[6]  += ea.w * yv.x;  acc[7]  += ea.w * yv.y;
    acc[8]  += eb.x * yv.x;  acc[9]  += eb.x * yv.y;
    acc[10] += eb.y * yv.x;  acc[11] += eb.y * yv.y;
    acc[12] += eb.z * yv.x;  acc[13] += eb.z * yv.y;
    acc[14] += eb.w * yv.x;  acc[15] += eb.w * yv.y;
}

__global__ void __launch_bounds__(256, 3) k_main(const float* __restrict__ bvec,
                                                 float* __restrict__ out, int N) {
    int w = (blockIdx.x * blockDim.x + threadIdx.x) >> 5;
    if (w >= N) return;
    int lane = threadIdx.x & 31;
    int beg = g_off[w], end = g_off[w + 1];   // multiples of 8

    float acc[16];
    #pragma unroll
    for (int a = 0; a < 16; a++) acc[a] = 0.f;

    const float* yb = g_y + lane * 2;

    for (int j = beg; j < end; j += 8) {
        int4 s0 = *(const int4*)(g_srcP + j);
        int4 s1 = *(const int4*)(g_srcP + j + 4);
        float2 y0 = *(const float2*)(yb + (size_t)s0.x * NF);
        float2 y1 = *(const float2*)(yb + (size_t)s0.y * NF);
        float2 y2 = *(const float2*)(yb + (size_t)s0.z * NF);
        float2 y3 = *(const float2*)(yb + (size_t)s0.w * NF);
        float2 y4 = *(const float2*)(yb + (size_t)s1.x * NF);
        float2 y5 = *(const float2*)(yb + (size_t)s1.y * NF);
        float2 y6 = *(const float2*)(yb + (size_t)s1.z * NF);
        float2 y7 = *(const float2*)(yb + (size_t)s1.w * NF);
        const float4* ep = (const float4*)(g_efP + (size_t)j * ED);
        fma_edge(acc, ep[0],  ep[1],  y0);
        fma_edge(acc, ep[2],  ep[3],  y1);
        fma_edge(acc, ep[4],  ep[5],  y2);
        fma_edge(acc, ep[6],  ep[7],  y3);
        fma_edge(acc, ep[8],  ep[9],  y4);
        fma_edge(acc, ep[10], ep[11], y5);
        fma_edge(acc, ep[12], ep[13], y6);
        fma_edge(acc, ep[14], ep[15], y7);
    }

    float2 bb = *(const float2*)(bvec + lane * 2);
    float* op = out + (size_t)w * (ED * NF);
    #pragma unroll
    for (int k = 0; k < ED; k++) {
        float2 v;
        v.x = acc[2 * k]     + bb.x;
        v.y = acc[2 * k + 1] + bb.y;
        *(float2*)(op + k * NF + lane * 2) = v;
    }
}

// ---------------- launch ----------------

extern "C" void kernel_launch(void* const* d_in, const int* in_sizes, int n_in,
                              void* d_out, int out_size) {
    const float* node_feat = (const float*)d_in[0];
    const float* edge_feat = (const float*)d_in[1];
    const float* W         = (const float*)d_in[2];
    const float* b         = (const float*)d_in[3];
    const int*   src       = (const int*)d_in[4];
    const int*   dst       = (const int*)d_in[5];

    int N = in_sizes[0] / NF;     // 50000
    int E = in_sizes[4];          // 800000
    int NB = (N + SCAN_B - 1) / SCAN_B;

    // Order chosen so launch index 3 (ncu capture slot) = k_ygemm.
    k_wt        <<<16, 256>>>(W);                                   // 0
    k_zero_deg  <<<(N + 255) / 256, 256>>>(N);                      // 1
    k_hist      <<<(E / 4 + 255) / 256, 256>>>(dst, E);             // 2
    k_ygemm     <<<(N + 31) / 32, 256>>>(node_feat, N);             // 3  <- profiled
    k_scanA     <<<NB, SCAN_B>>>(N);                                // 4
    k_scanB     <<<1, MAX_BLKS>>>(NB, N);                           // 5
    k_scanC     <<<(N + 255) / 256, 256>>>(N);                      // 6
    k_scatterpad<<<(E + 8 * N + 255) / 256, 256>>>(src, dst, edge_feat, E, N); // 7
    k_main      <<<(N * 32 + 255) / 256, 256>>>(b, (float*)d_out, N);          // 8
}

// round 6
// speedup vs baseline: 1.8319x; 1.1174x over previous
#include <cuda_runtime.h>

// EfConv: out[n, k*64+o] = sum_{e: dst_e=n} ef[e,k] * (node_feat[src_e] . W[o]) + b[o]
// y = X @ W^T first. CSR-by-dst with 8-aligned zero-padded segments; permuted
// src + ef payload; warp-per-node main pass (8-edge batches).
// R6: (a) ygemm forked onto a side stream (event fork/join, capture-legal) so
// the CSR chain hides it; (b) ygemm register-blocked 4 nodes/thread to halve
// smem traffic per FFMA.

#define MAXN 50000
#define MAXE 800000
#define NF 64
#define ED 8
#define MAXP (MAXE + 8 * MAXN)
#define SCAN_B 1024
#define MAX_BLKS 64

__device__ int   g_deg[MAXN];
__device__ int   g_off[MAXN + 1];
__device__ int   g_cur[MAXN];
__device__ int   g_bsum[MAX_BLKS];
__device__ int   g_boff[MAX_BLKS];
__device__ int   g_srcP[MAXP];
__device__ float g_efP[(size_t)MAXP * ED];
__device__ float g_y[(size_t)MAXN * NF];
__device__ float g_WT[NF * NF];              // g_WT[i*64+o] = W[o*64+i]

// ---------------- W transpose (tiny) ----------------
__global__ void k_wt(const float* __restrict__ W) {
    int idx = blockIdx.x * blockDim.x + threadIdx.x;
    if (idx < NF * NF)
        g_WT[(idx & 63) * NF + (idx >> 6)] = W[idx];
}

__global__ void k_zero_deg(int N) {
    int i = blockIdx.x * blockDim.x + threadIdx.x;
    if (i < N) g_deg[i] = 0;
}

__global__ void k_hist(const int* __restrict__ dst, int E) {
    int t = blockIdx.x * blockDim.x + threadIdx.x;
    int e = t * 4;
    if (e + 4 <= E) {
        int4 d = *(const int4*)(dst + e);
        atomicAdd(&g_deg[d.x], 1);
        atomicAdd(&g_deg[d.y], 1);
        atomicAdd(&g_deg[d.z], 1);
        atomicAdd(&g_deg[d.w], 1);
    } else {
        for (; e < E; e++) atomicAdd(&g_deg[dst[e]], 1);
    }
}

// ---------------- y = X @ W^T : 64 nodes/block, 4 nodes/thread ----------------
__global__ void __launch_bounds__(256) k_ygemm(const float* __restrict__ X, int N) {
    __shared__ float WsT[NF * NF];    // 16 KB, [i*64+o]
    __shared__ float xs[64][NF];      // 16 KB
    int t = threadIdx.x;
    int base = blockIdx.x * 64;

    #pragma unroll
    for (int k = 0; k < 4; k++)
        ((float4*)WsT)[t + k * 256] = ((const float4*)g_WT)[t + k * 256];
    #pragma unroll
    for (int k = 0; k < 4; k++) {
        int idx = t + k * 256;                 // float4 index into xs (1024 total)
        int ln = idx >> 4, q = idx & 15;
        int n = base + ln;
        float4 v = (n < N) ? ((const float4*)(X + (size_t)n * NF))[q]
                           : make_float4(0.f, 0.f, 0.f, 0.f);
        ((float4*)&xs[ln][0])[q] = v;
    }
    __syncthreads();

    int o4 = (t & 15) * 4;
    int slot = t >> 4;                         // 0..15; nodes slot, +16, +32, +48
    float4 a0 = make_float4(0.f, 0.f, 0.f, 0.f);
    float4 a1 = a0, a2 = a0, a3 = a0;
    #pragma unroll 8
    for (int i = 0; i < NF; i++) {
        float4 w = *(const float4*)&WsT[i * NF + o4];   // shared by 4 nodes
        float x0 = xs[slot][i];
        float x1 = xs[slot + 16][i];
        float x2 = xs[slot + 32][i];
        float x3 = xs[slot + 48][i];
        a0.x += w.x * x0; a0.y += w.y * x0; a0.z += w.z * x0; a0.w += w.w * x0;
        a1.x += w.x * x1; a1.y += w.y * x1; a1.z += w.z * x1; a1.w += w.w * x1;
        a2.x += w.x * x2; a2.y += w.y * x2; a2.z += w.z * x2; a2.w += w.w * x2;
        a3.x += w.x * x3; a3.y += w.y * x3; a3.z += w.z * x3; a3.w += w.w * x3;
    }
    int n0 = base + slot;
    if (n0 < N)      *(float4*)(g_y + (size_t)n0 * NF + o4) = a0;
    if (n0 + 16 < N) *(float4*)(g_y + (size_t)(n0 + 16) * NF + o4) = a1;
    if (n0 + 32 < N) *(float4*)(g_y + (size_t)(n0 + 32) * NF + o4) = a2;
    if (n0 + 48 < N) *(float4*)(g_y + (size_t)(n0 + 48) * NF + o4) = a3;
}

// ---------------- scan (3-pass, coalesced) ----------------
__global__ void k_scanA(int N) {
    __shared__ int sh[SCAN_B];
    int t = threadIdx.x;
    int i = blockIdx.x * SCAN_B + t;
    int v = (i < N) ? ((g_deg[i] + 7) & ~7) : 0;
    sh[t] = v;
    __syncthreads();
    for (int d = 1; d < SCAN_B; d <<= 1) {
        int u = (t >= d) ? sh[t - d] : 0;
        __syncthreads();
        sh[t] += u;
        __syncthreads();
    }
    if (i < N) g_off[i] = sh[t] - v;
    if (t == SCAN_B - 1) g_bsum[blockIdx.x] = sh[SCAN_B - 1];
}

__global__ void k_scanB(int NB, int N) {
    __shared__ int sh[MAX_BLKS];
    int t = threadIdx.x;
    int v = (t < NB) ? g_bsum[t] : 0;
    sh[t] = v;
    __syncthreads();
    for (int d = 1; d < MAX_BLKS; d <<= 1) {
        int u = (t >= d) ? sh[t - d] : 0;
        __syncthreads();
        sh[t] += u;
        __syncthreads();
    }
    if (t < NB) g_boff[t] = sh[t] - v;
    if (t == MAX_BLKS - 1) g_off[N] = sh[MAX_BLKS - 1];
}

__global__ void k_scanC(int N) {
    int i = blockIdx.x * blockDim.x + threadIdx.x;
    if (i < N) {
        int o = g_off[i] + g_boff[i >> 10];
        g_off[i] = o;
        g_cur[i] = o;
    }
}

// ---------------- scatter + pad (fused) ----------------
__global__ void k_scatterpad(const int* __restrict__ src, const int* __restrict__ dst,
                             const float* __restrict__ ef, int E, int N) {
    int t = blockIdx.x * blockDim.x + threadIdx.x;
    if (t < E) {
        int pos = atomicAdd(&g_cur[dst[t]], 1);
        g_srcP[pos] = src[t];
        const float4* s4 = (const float4*)(ef + (size_t)t * ED);
        float4 a = s4[0], c = s4[1];
        float4* o4 = (float4*)(g_efP + (size_t)pos * ED);
        o4[0] = a;
        o4[1] = c;
    } else {
        int idx = t - E;
        int i = idx >> 3, s = idx & 7;
        if (i < N) {
            int p = g_off[i] + g_deg[i] + s;
            if (p < g_off[i + 1]) {
                g_srcP[p] = 0;
                float4 z = make_float4(0.f, 0.f, 0.f, 0.f);
                float4* o4 = (float4*)(g_efP + (size_t)p * ED);
                o4[0] = z;
                o4[1] = z;
            }
        }
    }
}

// ---------------- main: warp-per-node, 8-edge batches ----------------
__device__ __forceinline__ void fma_edge(float (&acc)[16], float4 ea, float4 eb, float2 yv) {
    acc[0]  += ea.x * yv.x;  acc[1]  += ea.x * yv.y;
    acc[2]  += ea.y * yv.x;  acc[3]  += ea.y * yv.y;
    acc[4]  += ea.z * yv.x;  acc[5]  += ea.z * yv.y;
    acc[6]  += ea.w * yv.x;  acc[7]  += ea.w * yv.y;
    acc[8]  += eb.x * yv.x;  acc[9]  += eb.x * yv.y;
    acc[10] += eb.y * yv.x;  acc[11] += eb.y * yv.y;
    acc[12] += eb.z * yv.x;  acc[13] += eb.z * yv.y;
    acc[14] += eb.w * yv.x;  acc[15] += eb.w * yv.y;
}

__global__ void __launch_bounds__(256, 3) k_main(const float* __restrict__ bvec,
                                                 float* __restrict__ out, int N) {
    int w = (blockIdx.x * blockDim.x + threadIdx.x) >> 5;
    if (w >= N) return;
    int lane = threadIdx.x & 31;
    int beg = g_off[w], end = g_off[w + 1];   // multiples of 8

    float acc[16];
    #pragma unroll
    for (int a = 0; a < 16; a++) acc[a] = 0.f;

    const float* yb = g_y + lane * 2;

    for (int j = beg; j < end; j += 8) {
        int4 s0 = *(const int4*)(g_srcP + j);
        int4 s1 = *(const int4*)(g_srcP + j + 4);
        float2 y0 = *(const float2*)(yb + (size_t)s0.x * NF);
        float2 y1 = *(const float2*)(yb + (size_t)s0.y * NF);
        float2 y2 = *(const float2*)(yb + (size_t)s0.z * NF);
        float2 y3 = *(const float2*)(yb + (size_t)s0.w * NF);
        float2 y4 = *(const float2*)(yb + (size_t)s1.x * NF);
        float2 y5 = *(const float2*)(yb + (size_t)s1.y * NF);
        float2 y6 = *(const float2*)(yb + (size_t)s1.z * NF);
        float2 y7 = *(const float2*)(yb + (size_t)s1.w * NF);
        const float4* ep = (const float4*)(g_efP + (size_t)j * ED);
        fma_edge(acc, ep[0],  ep[1],  y0);
        fma_edge(acc, ep[2],  ep[3],  y1);
        fma_edge(acc, ep[4],  ep[5],  y2);
        fma_edge(acc, ep[6],  ep[7],  y3);
        fma_edge(acc, ep[8],  ep[9],  y4);
        fma_edge(acc, ep[10], ep[11], y5);
        fma_edge(acc, ep[12], ep[13], y6);
        fma_edge(acc, ep[14], ep[15], y7);
    }

    float2 bb = *(const float2*)(bvec + lane * 2);
    float* op = out + (size_t)w * (ED * NF);
    #pragma unroll
    for (int k = 0; k < ED; k++) {
        float2 v;
        v.x = acc[2 * k]     + bb.x;
        v.y = acc[2 * k + 1] + bb.y;
        *(float2*)(op + k * NF + lane * 2) = v;
    }
}

// ---------------- launch ----------------

extern "C" void kernel_launch(void* const* d_in, const int* in_sizes, int n_in,
                              void* d_out, int out_size) {
    const float* node_feat = (const float*)d_in[0];
    const float* edge_feat = (const float*)d_in[1];
    const float* W         = (const float*)d_in[2];
    const float* b         = (const float*)d_in[3];
    const int*   src       = (const int*)d_in[4];
    const int*   dst       = (const int*)d_in[5];

    int N = in_sizes[0] / NF;     // 50000
    int E = in_sizes[4];          // 800000
    int NB = (N + SCAN_B - 1) / SCAN_B;

    // Side stream for the (X,W)-only GEMM chain; fork/join via events is
    // graph-capture legal. Host objects only (no device memory); created per
    // call so every invocation does identical work. Not destroyed (destroying
    // a stream used in an ongoing capture is illegal); leak is a few host
    // objects per call.
    cudaStream_t s2;
    cudaStreamCreateWithFlags(&s2, cudaStreamNonBlocking);
    cudaEvent_t evF, evJ;
    cudaEventCreateWithFlags(&evF, cudaEventDisableTiming);
    cudaEventCreateWithFlags(&evJ, cudaEventDisableTiming);

    // Fork s2 off the main (captured) stream.
    cudaEventRecord(evF, 0);
    cudaStreamWaitEvent(s2, evF, 0);

    // Issue order (ncu capture slot = launch index 3 -> k_ygemm):
    k_zero_deg  <<<(N + 255) / 256, 256>>>(N);                       // 0
    k_hist      <<<(E / 4 + 255) / 256, 256>>>(dst, E);              // 1
    k_wt        <<<16, 256, 0, s2>>>(W);                             // 2
    k_ygemm     <<<(N + 63) / 64, 256, 0, s2>>>(node_feat, N);       // 3 <- profiled
    cudaEventRecord(evJ, s2);

    k_scanA     <<<NB, SCAN_B>>>(N);                                 // 4
    k_scanB     <<<1, MAX_BLKS>>>(NB, N);                            // 5
    k_scanC     <<<(N + 255) / 256, 256>>>(N);                       // 6
    k_scatterpad<<<(E + 8 * N + 255) / 256, 256>>>(src, dst, edge_feat, E, N); // 7

    // Join: k_main needs both the CSR chain (stream 0) and y (s2).
    cudaStreamWaitEvent(0, evJ, 0);
    k_main      <<<(N * 32 + 255) / 256, 256>>>(b, (float*)d_out, N);          // 8
}